// round 17
// baseline (speedup 1.0000x reference)
#include <cuda_runtime.h>
#include <cuda_bf16.h>
#include <cuda_fp16.h>
#include <cfloat>

// ---------------------------------------------------------------------------
//   N = 500000 rows, D = 64, G = 50000 groups, w1: [192,64], w2: [64,64]
// Algebra: h@w1 = x@(w1a+w1b+w1c) - min_g@w1b - max_g@w1c
//   => y1 = leaky(x@Wsum + bias[seg]),  out = leaky(y1@w2)
// All GEMMs on fp16 mma.sync m16n8k16: weights hi/lo 2-term, activations
// single fp16, fp32 accumulate. Fused kernel: 2-phase, y1 via smem,
// persistent tile loop, 4 blocks/SM.
// ---------------------------------------------------------------------------

#define MAX_G 50000
#define MAX_N 500000

__device__ float    g_bias[MAX_G * 64];
__device__ int      g_seg[MAX_N];
__device__ __align__(16) unsigned g_nm16[MAX_G * 64];
__device__ __align__(16) unsigned g_wall[4 * 64 * 36];
__device__ __align__(16) unsigned g_wbias[2 * 64 * 68];

__device__ __forceinline__ float lrelu(float v) { return v > 0.0f ? v : 0.2f * v; }

// ---- fp16 / mma helpers ----------------------------------------------------
__device__ __forceinline__ unsigned cvt2h(float hi, float lo) {   // low half = lo
    unsigned r;
    asm("cvt.rn.f16x2.f32 %0, %1, %2;" : "=r"(r) : "f"(hi), "f"(lo));
    return r;
}
__device__ __forceinline__ unsigned smu32(const void* p) {
    unsigned r;
    asm("{.reg .u64 t; cvta.to.shared.u64 t, %1; cvt.u32.u64 %0, t;}" : "=r"(r) : "l"(p));
    return r;
}
__device__ __forceinline__ void ldsm4(unsigned& r0, unsigned& r1,
                                      unsigned& r2, unsigned& r3, unsigned addr) {
    asm volatile("ldmatrix.sync.aligned.m8n8.x4.shared.b16 {%0,%1,%2,%3}, [%4];"
                 : "=r"(r0), "=r"(r1), "=r"(r2), "=r"(r3) : "r"(addr));
}
__device__ __forceinline__ void mma16816h(float* c, const unsigned* a,
                                          unsigned b0, unsigned b1) {
    asm volatile(
        "mma.sync.aligned.m16n8k16.row.col.f32.f16.f16.f32 "
        "{%0,%1,%2,%3}, {%4,%5,%6,%7}, {%8,%9}, {%0,%1,%2,%3};"
        : "+f"(c[0]), "+f"(c[1]), "+f"(c[2]), "+f"(c[3])
        : "r"(a[0]), "r"(a[1]), "r"(a[2]), "r"(a[3]), "r"(b0), "r"(b1));
}

// ---------------------------------------------------------------------------
// Kernel 0: precompute all fp16 hi/lo split weights (transposed, [n][k])
// ---------------------------------------------------------------------------
__global__ void prep_weights_kernel(const float* __restrict__ w1,
                                    const float* __restrict__ w2) {
    int t = blockIdx.x * 256 + threadIdx.x;

    if (t < 2048) {
        int nn = t >> 5;
        int k2 = t & 31;
        int k  = k2 * 2;
        float ws0 = w1[k * 64 + nn] + w1[(k + 64) * 64 + nn] + w1[(k + 128) * 64 + nn];
        float ws1 = w1[(k + 1) * 64 + nn] + w1[(k + 65) * 64 + nn] + w1[(k + 129) * 64 + nn];
        __half h0 = __float2half_rn(ws0);
        __half h1 = __float2half_rn(ws1);
        __half l0 = __float2half_rn(ws0 - __half2float(h0));
        __half l1 = __float2half_rn(ws1 - __half2float(h1));
        int idx = nn * 36 + k2;
        g_wall[0 * 2304 + idx] = ((unsigned)__half_as_ushort(h1) << 16) | __half_as_ushort(h0);
        g_wall[1 * 2304 + idx] = ((unsigned)__half_as_ushort(l1) << 16) | __half_as_ushort(l0);

        float v0 = w2[k * 64 + nn];
        float v1 = w2[(k + 1) * 64 + nn];
        __half p0 = __float2half_rn(v0);
        __half p1 = __float2half_rn(v1);
        __half q0 = __float2half_rn(v0 - __half2float(p0));
        __half q1 = __float2half_rn(v1 - __half2float(p1));
        g_wall[2 * 2304 + idx] = ((unsigned)__half_as_ushort(p1) << 16) | __half_as_ushort(p0);
        g_wall[3 * 2304 + idx] = ((unsigned)__half_as_ushort(q1) << 16) | __half_as_ushort(q0);
    } else if (t < 2048 + 4096) {
        int j  = t - 2048;
        int nn = j >> 6;
        int k2 = j & 63;
        int k  = k2 * 2;
        float b0 = w1[(64 + k) * 64 + nn];
        float b1 = w1[(64 + k + 1) * 64 + nn];
        __half h0 = __float2half_rn(b0);
        __half h1 = __float2half_rn(b1);
        __half l0 = __float2half_rn(b0 - __half2float(h0));
        __half l1 = __float2half_rn(b1 - __half2float(h1));
        int idx = nn * 68 + k2;
        g_wbias[idx]        = ((unsigned)__half_as_ushort(h1) << 16) | __half_as_ushort(h0);
        g_wbias[4352 + idx] = ((unsigned)__half_as_ushort(l1) << 16) | __half_as_ushort(l0);
    }
}

// ---------------------------------------------------------------------------
// Kernel 1: per-group min/max -> fp16 negated [-min|-max] + seg map.
// ---------------------------------------------------------------------------
__global__ __launch_bounds__(256) void minmax_kernel(
    const float* __restrict__ x, const int* __restrict__ csr, int G)
{
    int tid  = threadIdx.x;
    int w    = tid >> 5;
    int lane = tid & 31;
    int half = lane >> 4;
    int hl   = lane & 15;
    int c    = hl * 4;
    int totalWarps = gridDim.x * 8;

    for (int g = blockIdx.x * 8 + w; g < G; g += totalWarps) {
        int s = csr[g];
        int e = csr[g + 1];

        float4 mn = make_float4( FLT_MAX,  FLT_MAX,  FLT_MAX,  FLT_MAX);
        float4 mx = make_float4(-FLT_MAX, -FLT_MAX, -FLT_MAX, -FLT_MAX);

        int r = s + half;
        for (; r + 2 < e; r += 4) {
            float4 v0 = *(const float4*)(x + (long long)r * 64 + c);
            float4 v1 = *(const float4*)(x + (long long)(r + 2) * 64 + c);
            mn.x = fminf(mn.x, fminf(v0.x, v1.x));  mn.y = fminf(mn.y, fminf(v0.y, v1.y));
            mn.z = fminf(mn.z, fminf(v0.z, v1.z));  mn.w = fminf(mn.w, fminf(v0.w, v1.w));
            mx.x = fmaxf(mx.x, fmaxf(v0.x, v1.x));  mx.y = fmaxf(mx.y, fmaxf(v0.y, v1.y));
            mx.z = fmaxf(mx.z, fmaxf(v0.z, v1.z));  mx.w = fmaxf(mx.w, fmaxf(v0.w, v1.w));
        }
        for (; r < e; r += 2) {
            float4 v = *(const float4*)(x + (long long)r * 64 + c);
            mn.x = fminf(mn.x, v.x);  mn.y = fminf(mn.y, v.y);
            mn.z = fminf(mn.z, v.z);  mn.w = fminf(mn.w, v.w);
            mx.x = fmaxf(mx.x, v.x);  mx.y = fmaxf(mx.y, v.y);
            mx.z = fmaxf(mx.z, v.z);  mx.w = fmaxf(mx.w, v.w);
        }

        mn.x = fminf(mn.x, __shfl_xor_sync(0xffffffffu, mn.x, 16));
        mn.y = fminf(mn.y, __shfl_xor_sync(0xffffffffu, mn.y, 16));
        mn.z = fminf(mn.z, __shfl_xor_sync(0xffffffffu, mn.z, 16));
        mn.w = fminf(mn.w, __shfl_xor_sync(0xffffffffu, mn.w, 16));
        mx.x = fmaxf(mx.x, __shfl_xor_sync(0xffffffffu, mx.x, 16));
        mx.y = fmaxf(mx.y, __shfl_xor_sync(0xffffffffu, mx.y, 16));
        mx.z = fmaxf(mx.z, __shfl_xor_sync(0xffffffffu, mx.z, 16));
        mx.w = fmaxf(mx.w, __shfl_xor_sync(0xffffffffu, mx.w, 16));

        if (s == e) {
            mn = make_float4(0.f, 0.f, 0.f, 0.f);
            mx = make_float4(0.f, 0.f, 0.f, 0.f);
        }

        for (int rr = s + lane; rr < e; rr += 32) g_seg[rr] = g;

        if (half == 0) {
            *(uint2*)(g_nm16 + g * 64 + hl * 2) =
                make_uint2(cvt2h(-mn.y, -mn.x), cvt2h(-mn.w, -mn.z));
            *(uint2*)(g_nm16 + g * 64 + 32 + hl * 2) =
                make_uint2(cvt2h(-mx.y, -mx.x), cvt2h(-mx.w, -mx.z));
        }
    }
}

// ---------------------------------------------------------------------------
// Kernel 2: bias GEMM on fp16 mma (unchanged from R15).
// ---------------------------------------------------------------------------
#define BST 136
#define SM_AB 34816
#define BIAS_SMEM_BYTES (34816 + 128 * BST * 2)   // 69632

__global__ __launch_bounds__(128) void bias_mma_kernel(int G)
{
    extern __shared__ __align__(16) char smraw[];
    __half* As = (__half*)(smraw + SM_AB);

    int tid = threadIdx.x;
    int G0  = blockIdx.x * 128;

    {
        const uint4* src = (const uint4*)g_wbias;
        uint4* dst = (uint4*)smraw;
        #pragma unroll
        for (int j = 0; j < 17; ++j) dst[tid + j * 128] = src[tid + j * 128];
    }
    {
        const uint4* nm = (const uint4*)g_nm16;
        #pragma unroll
        for (int j = 0; j < 16; ++j) {
            int i = tid + j * 128;
            int r = i >> 4;
            int q = i & 15;
            int g = G0 + r;
            uint4 v = make_uint4(0u, 0u, 0u, 0u);
            if (g < G) v = nm[(long long)g * 16 + q];
            *(uint4*)((char*)As + r * 272 + q * 16) = v;
        }
    }
    __syncthreads();

    int lane = tid & 31;
    int w    = tid >> 5;
    int rowq = lane >> 2;
    int kq   = (lane & 3) * 2;
    int W0   = w * 32;
    int lrow = lane & 15;
    int lcol = (lane >> 4) * 8;

    unsigned aB0 = smu32(As) + (unsigned)(((W0 + lrow) * BST + lcol) * 2);
    unsigned aB1 = aB0 + 16u * 272u;

    unsigned wb = smu32(smraw);
    unsigned laneB = (unsigned)((((lane & 7) + ((lane >> 4) << 3)) * 272) +
                                (((lane >> 3) & 1) * 16));
    unsigned b_h = wb + laneB;
    unsigned b_l = b_h + 17408u;

    float acc[2][8][4];
    #pragma unroll
    for (int mt = 0; mt < 2; ++mt)
        #pragma unroll
        for (int nt = 0; nt < 8; ++nt)
            #pragma unroll
            for (int u = 0; u < 4; ++u) acc[mt][nt][u] = 0.f;

    #pragma unroll
    for (int kt = 0; kt < 8; ++kt) {
        unsigned a0[4], a1[4];
        ldsm4(a0[0], a0[1], a0[2], a0[3], aB0 + kt * 32);
        ldsm4(a1[0], a1[1], a1[2], a1[3], aB1 + kt * 32);
        #pragma unroll
        for (int q = 0; q < 4; ++q) {
            unsigned b0, b1, b2, b3;
            ldsm4(b0, b1, b2, b3, b_h + q * 16 * 272 + kt * 32);
            mma16816h(acc[0][2 * q],     a0, b0, b1);
            mma16816h(acc[1][2 * q],     a1, b0, b1);
            mma16816h(acc[0][2 * q + 1], a0, b2, b3);
            mma16816h(acc[1][2 * q + 1], a1, b2, b3);
        }
        #pragma unroll
        for (int q = 0; q < 4; ++q) {
            unsigned b0, b1, b2, b3;
            ldsm4(b0, b1, b2, b3, b_l + q * 16 * 272 + kt * 32);
            mma16816h(acc[0][2 * q],     a0, b0, b1);
            mma16816h(acc[1][2 * q],     a1, b0, b1);
            mma16816h(acc[0][2 * q + 1], a0, b2, b3);
            mma16816h(acc[1][2 * q + 1], a1, b2, b3);
        }
    }

    #pragma unroll
    for (int mt = 0; mt < 2; ++mt) {
        int glo = G0 + W0 + mt * 16 + rowq;
        int ghi = glo + 8;
        #pragma unroll
        for (int nt = 0; nt < 8; ++nt) {
            int col = nt * 8 + kq;
            if (glo < G)
                *(float2*)(g_bias + (long long)glo * 64 + col) =
                    make_float2(acc[mt][nt][0], acc[mt][nt][1]);
            if (ghi < G)
                *(float2*)(g_bias + (long long)ghi * 64 + col) =
                    make_float2(acc[mt][nt][2], acc[mt][nt][3]);
        }
    }
}

// ---------------------------------------------------------------------------
// Kernel 3: fused MLP, 2-phase with y1 staged via smem. 128 rows/tile,
// 4 warps m32/warp, persistent tile loop, 4 blocks/SM.
// ---------------------------------------------------------------------------
#define XST 72
#define NROWS 128
#define SM_XS  36864
#define MMA_SMEM_BYTES (36864 + NROWS * XST * 2)   // 55296

__global__ __launch_bounds__(128, 4) void fused_mma_kernel(
    const float* __restrict__ x, float* __restrict__ out, int n, int ntiles)
{
    extern __shared__ __align__(16) char smraw[];
    __half* xs = (__half*)(smraw + SM_XS);

    int tid = threadIdx.x;

    // stage weights once per block
    {
        const uint4* src = (const uint4*)g_wall;
        uint4* dst = (uint4*)smraw;
        #pragma unroll
        for (int j = 0; j < 18; ++j) dst[tid + j * 128] = src[tid + j * 128];
    }

    int lane = tid & 31;
    int w    = tid >> 5;
    int rowq = lane >> 2;
    int kq   = (lane & 3) * 2;
    int W0   = w * 32;
    int lrow = lane & 15;
    int lcol = (lane >> 4) * 8;

    unsigned xs_u = smu32(xs);
    unsigned aA0 = xs_u + (unsigned)(((W0 + lrow) * XST + lcol) * 2);
    unsigned aA1 = aA0 + 16u * XST * 2u;

    unsigned wb = smu32(smraw);
    unsigned laneB = (unsigned)((((lane & 7) + ((lane >> 4) << 3)) * 144) +
                                (((lane >> 3) & 1) * 16));
    unsigned b_w1h = wb + 0 * 9216 + laneB;
    unsigned b_w1l = wb + 1 * 9216 + laneB;
    unsigned b_w2h = wb + 2 * 9216 + laneB;
    unsigned b_w2l = wb + 3 * 9216 + laneB;

    for (int tile = blockIdx.x; tile < ntiles; tile += gridDim.x) {
        int R0 = tile * NROWS;

        __syncthreads();   // xs free (prev tile phase-2 reads done)

        // stage x -> fp16
        #pragma unroll
        for (int j = 0; j < 16; ++j) {
            int i  = tid + j * 128;
            int r  = i >> 4;
            int c4 = (i & 15) * 4;
            int gr = R0 + r;
            float4 v = make_float4(0.f, 0.f, 0.f, 0.f);
            if (gr < n) v = *(const float4*)(x + (long long)gr * 64 + c4);
            *(uint2*)(xs + r * XST + c4) = make_uint2(cvt2h(v.y, v.x), cvt2h(v.w, v.z));
        }
        __syncthreads();

        // ---- phase 1: acc = x @ Wsum ----
        float acc[2][8][4];
        #pragma unroll
        for (int mt = 0; mt < 2; ++mt)
            #pragma unroll
            for (int nt = 0; nt < 8; ++nt)
                #pragma unroll
                for (int u = 0; u < 4; ++u) acc[mt][nt][u] = 0.f;

        #pragma unroll
        for (int kt = 0; kt < 4; ++kt) {
            unsigned a0[4], a1[4];
            ldsm4(a0[0], a0[1], a0[2], a0[3], aA0 + kt * 32);
            ldsm4(a1[0], a1[1], a1[2], a1[3], aA1 + kt * 32);
            #pragma unroll
            for (int q = 0; q < 4; ++q) {
                unsigned b0, b1, b2, b3;
                ldsm4(b0, b1, b2, b3, b_w1h + q * 16 * 144 + kt * 32);
                mma16816h(acc[0][2 * q],     a0, b0, b1);
                mma16816h(acc[1][2 * q],     a1, b0, b1);
                mma16816h(acc[0][2 * q + 1], a0, b2, b3);
                mma16816h(acc[1][2 * q + 1], a1, b2, b3);
            }
            #pragma unroll
            for (int q = 0; q < 4; ++q) {
                unsigned b0, b1, b2, b3;
                ldsm4(b0, b1, b2, b3, b_w1l + q * 16 * 144 + kt * 32);
                mma16816h(acc[0][2 * q],     a0, b0, b1);
                mma16816h(acc[1][2 * q],     a1, b0, b1);
                mma16816h(acc[0][2 * q + 1], a0, b2, b3);
                mma16816h(acc[1][2 * q + 1], a1, b2, b3);
            }
        }

        __syncthreads();   // all phase-1 reads of xs finished

        // ---- bias + leaky -> y1 (fp16) into xs ----
        #pragma unroll
        for (int mt = 0; mt < 2; ++mt) {
            int rlo = R0 + W0 + mt * 16 + rowq;
            int rhi = rlo + 8;
            int glo = (rlo < n) ? g_seg[rlo] : 0;
            int ghi = (rhi < n) ? g_seg[rhi] : 0;
            int rowlo = W0 + mt * 16 + rowq;
            #pragma unroll
            for (int nt = 0; nt < 8; ++nt) {
                int col = nt * 8 + kq;
                float2 blo = *(const float2*)(g_bias + (long long)glo * 64 + col);
                float2 bhi = *(const float2*)(g_bias + (long long)ghi * 64 + col);
                float y0 = lrelu(acc[mt][nt][0] + blo.x);
                float y1 = lrelu(acc[mt][nt][1] + blo.y);
                float y2 = lrelu(acc[mt][nt][2] + bhi.x);
                float y3 = lrelu(acc[mt][nt][3] + bhi.y);
                *(unsigned*)((char*)xs + (rowlo * XST + col) * 2)       = cvt2h(y1, y0);
                *(unsigned*)((char*)xs + ((rowlo + 8) * XST + col) * 2) = cvt2h(y3, y2);
            }
        }
        __syncthreads();

        // ---- phase 2: acc = y1 @ w2 (acc registers reused) ----
        #pragma unroll
        for (int mt = 0; mt < 2; ++mt)
            #pragma unroll
            for (int nt = 0; nt < 8; ++nt)
                #pragma unroll
                for (int u = 0; u < 4; ++u) acc[mt][nt][u] = 0.f;

        #pragma unroll
        for (int kt = 0; kt < 4; ++kt) {
            unsigned a0[4], a1[4];
            ldsm4(a0[0], a0[1], a0[2], a0[3], aA0 + kt * 32);
            ldsm4(a1[0], a1[1], a1[2], a1[3], aA1 + kt * 32);
            #pragma unroll
            for (int q = 0; q < 4; ++q) {
                unsigned b0, b1, b2, b3;
                ldsm4(b0, b1, b2, b3, b_w2h + q * 16 * 144 + kt * 32);
                mma16816h(acc[0][2 * q],     a0, b0, b1);
                mma16816h(acc[1][2 * q],     a1, b0, b1);
                mma16816h(acc[0][2 * q + 1], a0, b2, b3);
                mma16816h(acc[1][2 * q + 1], a1, b2, b3);
            }
            #pragma unroll
            for (int q = 0; q < 4; ++q) {
                unsigned b0, b1, b2, b3;
                ldsm4(b0, b1, b2, b3, b_w2l + q * 16 * 144 + kt * 32);
                mma16816h(acc[0][2 * q],     a0, b0, b1);
                mma16816h(acc[1][2 * q],     a1, b0, b1);
                mma16816h(acc[0][2 * q + 1], a0, b2, b3);
                mma16816h(acc[1][2 * q + 1], a1, b2, b3);
            }
        }

        // ---- epilogue: leaky + float2 stores ----
        #pragma unroll
        for (int mt = 0; mt < 2; ++mt) {
            int rlo = R0 + W0 + mt * 16 + rowq;
            int rhi = rlo + 8;
            #pragma unroll
            for (int nt = 0; nt < 8; ++nt) {
                int col = nt * 8 + kq;
                if (rlo < n)
                    *(float2*)(out + (long long)rlo * 64 + col) =
                        make_float2(lrelu(acc[mt][nt][0]), lrelu(acc[mt][nt][1]));
                if (rhi < n)
                    *(float2*)(out + (long long)rhi * 64 + col) =
                        make_float2(lrelu(acc[mt][nt][2]), lrelu(acc[mt][nt][3]));
            }
        }
    }
}

// ---------------------------------------------------------------------------
// Launch
// ---------------------------------------------------------------------------
extern "C" void kernel_launch(void* const* d_in, const int* in_sizes, int n_in,
                              void* d_out, int out_size)
{
    const float* x   = (const float*)d_in[0];
    const int*   csr = (const int*)  d_in[1];
    const float* w1  = (const float*)d_in[2];
    const float* w2  = (const float*)d_in[3];
    float*       out = (float*)d_out;

    int n = in_sizes[0] / 64;      // 500000
    int G = in_sizes[1] - 1;       // 50000
    int ntiles = (n + NROWS - 1) / NROWS;

    cudaFuncSetAttribute(bias_mma_kernel,
                         cudaFuncAttributeMaxDynamicSharedMemorySize, BIAS_SMEM_BYTES);
    cudaFuncSetAttribute(fused_mma_kernel,
                         cudaFuncAttributeMaxDynamicSharedMemorySize, MMA_SMEM_BYTES);

    int grid = 592;                // 4 blocks/SM target
    if (grid > ntiles) grid = ntiles;

    prep_weights_kernel<<<24, 256>>>(w1, w2);
    minmax_kernel<<<2048, 256>>>(x, csr, G);
    bias_mma_kernel<<<(G + 127) / 128, 128, BIAS_SMEM_BYTES>>>(G);
    fused_mma_kernel<<<grid, 128, MMA_SMEM_BYTES>>>(x, out, n, ntiles);
}